// round 10
// baseline (speedup 1.0000x reference)
#include <cuda_runtime.h>
#include <cuda_fp16.h>
#include <cstdint>
#include <cstddef>

// Problem dims (fixed)
#define M1 16384      // b*t*s = 16*4*256
#define K1 512        // d
#define N1 2048       // hidden
#define N2 512
#define HID 2048
#define N_SPIKES 33554432.0f  // 2^25

#define TAU 4e-3f     // borderline window; sigma_v ~ 4e-4 -> 10 sigma margin
#define FCAP (1 << 22)

// ---------------------------------------------------------------------------
// Device scratch (no allocation allowed).
// Spikes are BIT-PACKED: row rp = (b*256+s)*4 + t, 2048 bits (64 words) per row.
// ---------------------------------------------------------------------------
__device__ __half   g_x16[(size_t)M1 * K1];        // fp16(x), (b,s,t) row order
__device__ __half   g_w1h[(size_t)N1 * K1];        // fp16(w1)
__device__ uint32_t g_spkbits[(size_t)M1 * HID / 32];  // 4 MB packed spikes
__device__ __half   g_w2h[(size_t)N2 * HID];       // fp16(w2)
__device__ int      g_count;
__device__ int      g_nflag;
__device__ int      g_flag[FCAP];

// ---------------------------------------------------------------------------
// PTX helpers (baseline sm_80+ ISA: cp.async / ldmatrix / mma.sync)
// ---------------------------------------------------------------------------
__device__ __forceinline__ uint32_t smem_u32(const void* p) {
    uint32_t a;
    asm("{ .reg .u64 t; cvta.to.shared.u64 t, %1; cvt.u32.u64 %0, t; }" : "=r"(a) : "l"(p));
    return a;
}
__device__ __forceinline__ void cp16(uint32_t saddr, const void* g) {
    asm volatile("cp.async.cg.shared.global [%0], [%1], 16;" :: "r"(saddr), "l"(g));
}
__device__ __forceinline__ void ldm_x4(uint32_t* r, uint32_t addr) {
    asm volatile("ldmatrix.sync.aligned.m8n8.x4.shared.b16 {%0,%1,%2,%3}, [%4];"
        : "=r"(r[0]), "=r"(r[1]), "=r"(r[2]), "=r"(r[3]) : "r"(addr));
}
__device__ __forceinline__ void mma16816(float* c, const uint32_t* a, uint32_t b0, uint32_t b1) {
    asm volatile("mma.sync.aligned.m16n8k16.row.col.f32.f16.f16.f32 "
        "{%0,%1,%2,%3}, {%4,%5,%6,%7}, {%8,%9}, {%0,%1,%2,%3};"
        : "+f"(c[0]), "+f"(c[1]), "+f"(c[2]), "+f"(c[3])
        : "r"(a[0]), "r"(a[1]), "r"(a[2]), "r"(a[3]), "r"(b0), "r"(b1));
}

// ---------------------------------------------------------------------------
// GEMM config: 128x128x64 tiles, 3-stage pipeline, 8 warps (32x64 per warp)
// ---------------------------------------------------------------------------
#define BM 128
#define BN 128
#define BK 64
#define STAGES 3
#define A_STAGE_BYTES (BM * BK * 2)                 // 16384
#define STAGE_BYTES   (A_STAGE_BYTES + BN * BK * 2) // 32768
#define SMEM_TOTAL    (STAGES * STAGE_BYTES)        // 98304 (>= 128*132*4 epi)

// fc1 loader: both operands fp16 via cp.async
__device__ __forceinline__ void load_stage_f16(uint32_t s_stage, const __half* Ag,
                                               const __half* Bg, int K, int k0, int tid) {
#pragma unroll
    for (int i = 0; i < 4; i++) {
        int c = tid + i * 256;
        int row = c >> 3, kc = c & 7;
        uint32_t so = s_stage + row * 128 + ((kc ^ (row & 7)) << 4);
        cp16(so, Ag + (long)row * K + k0 + kc * 8);
    }
#pragma unroll
    for (int i = 0; i < 4; i++) {
        int c = tid + i * 256;
        int row = c >> 3, kc = c & 7;
        uint32_t so = s_stage + A_STAGE_BYTES + row * 128 + ((kc ^ (row & 7)) << 4);
        cp16(so, Bg + (long)row * K + k0 + kc * 8);
    }
}

// fc2 loader: A decoded from packed spike bits via smem LUT, B via cp.async.
__device__ __forceinline__ void load_stage_bits(char* sm_stage, uint32_t s_stage_u32,
                                                const uint8_t* Abytes, const __half* Bg,
                                                const uint4* lut, int k0, int tid) {
#pragma unroll
    for (int i = 0; i < 4; i++) {
        int c = tid + i * 256;
        int row = c >> 3, kc = c & 7;
        uint32_t byte = Abytes[(size_t)row * 256 + (k0 >> 3) + kc];
        uint4 u = lut[byte];
        *(uint4*)(sm_stage + row * 128 + ((kc ^ (row & 7)) << 4)) = u;
    }
#pragma unroll
    for (int i = 0; i < 4; i++) {
        int c = tid + i * 256;
        int row = c >> 3, kc = c & 7;
        uint32_t so = s_stage_u32 + A_STAGE_BYTES + row * 128 + ((kc ^ (row & 7)) << 4);
        cp16(so, Bg + (long)row * HID + k0 + kc * 8);
    }
}

// Compute body for one BK stage (acc/lane/wm/wn in caller scope)
#define STAGE_COMPUTE(sa_, sb_)                                                    \
    _Pragma("unroll")                                                              \
    for (int ks = 0; ks < 4; ks++) {                                               \
        const int kch = (ks << 1) + (lane >> 4);                                   \
        uint32_t ar[2][4];                                                         \
        _Pragma("unroll")                                                          \
        for (int mt = 0; mt < 2; mt++) {                                           \
            int row = wm * 32 + mt * 16 + (lane & 15);                             \
            ldm_x4(ar[mt], (sa_) + row * 128 + ((kch ^ (row & 7)) << 4));          \
        }                                                                          \
        uint32_t br[4][4];                                                         \
        _Pragma("unroll")                                                          \
        for (int np = 0; np < 4; np++) {                                           \
            int row = wn * 64 + np * 16 + (lane & 15);                             \
            ldm_x4(br[np], (sb_) + row * 128 + ((kch ^ (row & 7)) << 4));          \
        }                                                                          \
        _Pragma("unroll")                                                          \
        for (int mt = 0; mt < 2; mt++)                                             \
            _Pragma("unroll")                                                      \
            for (int nt = 0; nt < 8; nt++)                                         \
                mma16816(acc[mt][nt], ar[mt], br[nt >> 1][nt & 1],                 \
                         br[nt >> 1][(nt & 1) + 2]);                               \
    }

// ---------------------------------------------------------------------------
// fc1 + fused LIF: A rows (b,s,t)-ordered; epilogue scans t in-tile and emits
// bit-packed spikes via warp ballot.
// ---------------------------------------------------------------------------
__global__ __launch_bounds__(256, 2) void hgemm_fc1_lif(const __half* __restrict__ A,
                                                        const __half* __restrict__ B) {
    extern __shared__ char sm[];
    const uint32_t s_base = smem_u32(sm);
    const int tid = threadIdx.x;
    const int wid = tid >> 5, lane = tid & 31;
    const int wm = wid & 3;
    const int wn = wid >> 2;
    const long bm = (long)blockIdx.y * BM;
    const long bn = (long)blockIdx.x * BN;

    const __half* Ag = A + bm * K1;
    const __half* Bg = B + bn * K1;

    float acc[2][8][4];
#pragma unroll
    for (int mt = 0; mt < 2; mt++)
#pragma unroll
        for (int nt = 0; nt < 8; nt++)
#pragma unroll
            for (int i = 0; i < 4; i++) acc[mt][nt][i] = 0.0f;

    const int iters = K1 / BK;
    load_stage_f16(s_base, Ag, Bg, K1, 0, tid);
    asm volatile("cp.async.commit_group;" ::: "memory");
    load_stage_f16(s_base + STAGE_BYTES, Ag, Bg, K1, BK, tid);
    asm volatile("cp.async.commit_group;" ::: "memory");
    for (int it = 0; it < iters; it++) {
        asm volatile("cp.async.wait_group 1;" ::: "memory");
        __syncthreads();
        const int nst = it + 2;
        if (nst < iters)
            load_stage_f16(s_base + (nst % STAGES) * STAGE_BYTES, Ag, Bg, K1, nst * BK, tid);
        asm volatile("cp.async.commit_group;" ::: "memory");
        const uint32_t sa = s_base + (it % STAGES) * STAGE_BYTES;
        STAGE_COMPUTE(sa, sa + A_STAGE_BYTES)
    }

    // drain all cp.async before repurposing smem
    asm volatile("cp.async.wait_group 0;" ::: "memory");
    __syncthreads();

    // spill accumulators to smem: h[row within tile][col within tile]
    float* smf = (float*)sm;                 // [128][132]
#pragma unroll
    for (int mt = 0; mt < 2; mt++)
#pragma unroll
        for (int nt = 0; nt < 8; nt++) {
            int r0 = wm * 32 + mt * 16 + (lane >> 2);
            int c  = wn * 64 + nt * 8 + (lane & 3) * 2;
            smf[r0 * 132 + c]       = acc[mt][nt][0];
            smf[r0 * 132 + c + 1]   = acc[mt][nt][1];
            smf[(r0 + 8) * 132 + c]     = acc[mt][nt][2];
            smf[(r0 + 8) * 132 + c + 1] = acc[mt][nt][3];
        }
    __syncthreads();

    // LIF scan: 32 groups x 128 cols; each warp covers 32 consecutive cols of
    // one group -> spike bits emitted with one ballot per timestep.
    int total = 0;
#pragma unroll
    for (int k16 = 0; k16 < 16; k16++) {
        int id = tid + k16 * 256;
        int q  = id >> 7;             // group within tile (0..31)
        int c  = id & 127;            // col within tile (consecutive per warp)
        long gq = blockIdx.y * 32 + q;        // global (b*256+s)
        long j  = bn + c;                     // hidden index

        float v = 0.0f;
        int cnt = 0;
        bool flagged = false;
#pragma unroll
        for (int t = 0; t < 4; t++) {
            float h = smf[(4 * q + t) * 132 + c];
            v = fmaf(0.95f, v, h);
            flagged |= fabsf(v - 1.0f) < TAU;
            bool fire = (v - 1.0f) > 0.0f;
            uint32_t m = __ballot_sync(0xffffffffu, fire);
            if (lane == 0)
                g_spkbits[(gq * 4 + t) * 64 + (j >> 5)] = m;
            cnt += fire ? 1 : 0;
            v = fire ? 0.0f : v;
        }
        if (flagged) {
            int slot = atomicAdd(&g_nflag, 1);
            if (slot < FCAP) g_flag[slot] = (int)(gq * 2048 + j);
        } else {
            total += cnt;
        }
    }
#pragma unroll
    for (int o = 16; o > 0; o >>= 1) total += __shfl_down_sync(0xffffffffu, total, o);
    if (lane == 0 && total) atomicAdd(&g_count, total);
}

// ---------------------------------------------------------------------------
// fc2: A decoded from spike bits via smem LUT; epilogue un-permutes rows.
// ---------------------------------------------------------------------------
__global__ __launch_bounds__(256, 2) void hgemm_fc2(const uint32_t* __restrict__ Abits,
                                                    const __half* __restrict__ B,
                                                    float* __restrict__ C) {
    extern __shared__ char sm[];
    __shared__ uint4 lut[256];              // byte -> 8 fp16 {0,1}
    const uint32_t s_base = smem_u32(sm);
    const int tid = threadIdx.x;
    const int wid = tid >> 5, lane = tid & 31;
    const int wm = wid & 3;
    const int wn = wid >> 2;
    const long bm = (long)blockIdx.y * BM;
    const long bn = (long)blockIdx.x * BN;

    // build decode LUT (one entry per thread)
    {
        uint32_t byte = (uint32_t)tid;       // 256 threads = 256 entries
        uint4 u;
        u.x = ((byte      & 1u) * 0x3C00u) | (((byte >> 1) & 1u) * 0x3C000000u);
        u.y = (((byte >> 2) & 1u) * 0x3C00u) | (((byte >> 3) & 1u) * 0x3C000000u);
        u.z = (((byte >> 4) & 1u) * 0x3C00u) | (((byte >> 5) & 1u) * 0x3C000000u);
        u.w = (((byte >> 6) & 1u) * 0x3C00u) | (((byte >> 7) & 1u) * 0x3C000000u);
        lut[byte] = u;
    }
    __syncthreads();

    const uint8_t* Ab = (const uint8_t*)Abits + bm * 256;   // 256 bytes/row
    const __half* Bg = B + bn * HID;

    float acc[2][8][4];
#pragma unroll
    for (int mt = 0; mt < 2; mt++)
#pragma unroll
        for (int nt = 0; nt < 8; nt++)
#pragma unroll
            for (int i = 0; i < 4; i++) acc[mt][nt][i] = 0.0f;

    const int iters = HID / BK;
    load_stage_bits(sm, s_base, Ab, Bg, lut, 0, tid);
    asm volatile("cp.async.commit_group;" ::: "memory");
    load_stage_bits(sm + STAGE_BYTES, s_base + STAGE_BYTES, Ab, Bg, lut, BK, tid);
    asm volatile("cp.async.commit_group;" ::: "memory");
    for (int it = 0; it < iters; it++) {
        asm volatile("cp.async.wait_group 1;" ::: "memory");
        __syncthreads();
        const int nst = it + 2;
        if (nst < iters) {
            int so = (nst % STAGES) * STAGE_BYTES;
            load_stage_bits(sm + so, s_base + so, Ab, Bg, lut, nst * BK, tid);
        }
        asm volatile("cp.async.commit_group;" ::: "memory");
        const uint32_t sa = s_base + (it % STAGES) * STAGE_BYTES;
        STAGE_COMPUTE(sa, sa + A_STAGE_BYTES)
    }

    // epilogue: map row' (b,s,t) -> out row (b,t,s)
#pragma unroll
    for (int mt = 0; mt < 2; mt++)
#pragma unroll
        for (int nt = 0; nt < 8; nt++) {
            long rp0 = bm + wm * 32 + mt * 16 + (lane >> 2);
            long rp1 = rp0 + 8;
            long c = bn + wn * 64 + nt * 8 + (lane & 3) * 2;
            long b0 = rp0 >> 10, s0 = (rp0 >> 2) & 255, t0 = rp0 & 3;
            long b1 = rp1 >> 10, s1 = (rp1 >> 2) & 255, t1 = rp1 & 3;
            long r0 = b0 * 1024 + t0 * 256 + s0;
            long r1 = b1 * 1024 + t1 * 256 + s1;
            *(float2*)(C + r0 * N2 + c) = make_float2(acc[mt][nt][0], acc[mt][nt][1]);
            *(float2*)(C + r1 * N2 + c) = make_float2(acc[mt][nt][2], acc[mt][nt][3]);
        }
}

// ---------------------------------------------------------------------------
// Casts. x cast also permutes rows (b,t,s) -> (b,s,t).
// ---------------------------------------------------------------------------
__global__ __launch_bounds__(256) void cast_x_perm_kernel(const float* __restrict__ x,
                                                          __half* __restrict__ out) {
    int i4 = blockIdx.x * blockDim.x + threadIdx.x;   // over M1*K1/4 float4s
    if (i4 >= M1 * K1 / 4) return;
    int row = i4 >> 7;            // 128 float4 per row (K1=512)
    int within = i4 & 127;
    int b = row >> 10, t = (row >> 8) & 3, s = row & 255;
    long newrow = (((long)b * 256 + s) * 4 + t);
    float4 v = ((const float4*)x)[i4];
    __half2* dst = (__half2*)(out + newrow * K1 + within * 4);
    dst[0] = __floats2half2_rn(v.x, v.y);
    dst[1] = __floats2half2_rn(v.z, v.w);
}

__global__ __launch_bounds__(256) void cast16_kernel(const float* __restrict__ in,
                                                     __half* __restrict__ out, int n4) {
    int i = blockIdx.x * blockDim.x + threadIdx.x;
    if (i >= n4) return;
    float4 v = ((const float4*)in)[i];
    ((__half2*)out)[2 * i]     = __floats2half2_rn(v.x, v.y);
    ((__half2*)out)[2 * i + 1] = __floats2half2_rn(v.z, v.w);
}

__global__ void zero_count_kernel() { g_count = 0; g_nflag = 0; }

// ---------------------------------------------------------------------------
// Exact fixup for flagged neurons (bit-identical to R1's 0-flip arithmetic).
// Flips packed spike bits with atomicOr/atomicAnd.
// ---------------------------------------------------------------------------
__global__ __launch_bounds__(128) void fixup_kernel(const float* __restrict__ x,
                                                    const float* __restrict__ w1) {
    int n = g_nflag;
    if (n > FCAP) n = FCAP;
    const int stride = gridDim.x * blockDim.x;

    for (int i = blockIdx.x * blockDim.x + threadIdx.x; i < n; i += stride) {
        int idx = g_flag[i];
        int j  = idx & (HID - 1);
        int gq = idx >> 11;           // b*256 + s
        int b  = gq >> 8;
        int s  = gq & 255;
        const float4* wrow = (const float4*)(w1 + (size_t)j * K1);
        const uint32_t bit = 1u << (j & 31);

        float v = 0.0f;
        int c = 0;
#pragma unroll
        for (int tt = 0; tt < 4; tt++) {
            const float4* xrow = (const float4*)(x + (((size_t)b * 4 + tt) * 256 + s) * K1);
            float h = 0.0f;
            for (int k = 0; k < K1 / 4; k++) {
                float4 xv = __ldg(xrow + k);
                float4 wv = __ldg(wrow + k);
                h = fmaf(xv.x, wv.x, h);
                h = fmaf(xv.y, wv.y, h);
                h = fmaf(xv.z, wv.z, h);
                h = fmaf(xv.w, wv.w, h);
            }
            v = fmaf(0.95f, v, h);
            bool fire = (v - 1.0f) > 0.0f;
            size_t word = ((size_t)gq * 4 + tt) * 64 + (j >> 5);
            if (fire) atomicOr(&g_spkbits[word], bit);
            else      atomicAnd(&g_spkbits[word], ~bit);
            c += fire ? 1 : 0;
            v = fire ? 0.0f : v;
        }
        if (c) atomicAdd(&g_count, c);
    }
}

__global__ void write_rate_kernel(float* __restrict__ out, int pos) {
    out[pos] = (float)g_count * (1.0f / N_SPIKES);  // exact: count / 2^25
}

// ---------------------------------------------------------------------------
extern "C" void kernel_launch(void* const* d_in, const int* in_sizes, int n_in,
                              void* d_out, int out_size) {
    const float* x  = (const float*)d_in[0];  // (16,4,256,512)
    const float* w1 = (const float*)d_in[1];  // (2048,512)
    const float* w2 = (const float*)d_in[2];  // (512,2048)
    float* out = (float*)d_out;

    __half *x16, *w1h, *w2h;
    uint32_t* spkbits;
    cudaGetSymbolAddress((void**)&x16, g_x16);
    cudaGetSymbolAddress((void**)&w1h, g_w1h);
    cudaGetSymbolAddress((void**)&spkbits, g_spkbits);
    cudaGetSymbolAddress((void**)&w2h, g_w2h);

    cudaFuncSetAttribute(hgemm_fc1_lif, cudaFuncAttributeMaxDynamicSharedMemorySize, SMEM_TOTAL);
    cudaFuncSetAttribute(hgemm_fc2, cudaFuncAttributeMaxDynamicSharedMemorySize, SMEM_TOTAL);

    dim3 blk(256);

    zero_count_kernel<<<1, 1>>>();

    // fp16 casts (x also row-permuted to (b,s,t))
    cast_x_perm_kernel<<<(M1 * K1 / 4 + 255) / 256, blk>>>(x, x16);
    cast16_kernel<<<(N1 * K1 / 4 + 255) / 256, blk>>>(w1, w1h, N1 * K1 / 4);
    cast16_kernel<<<(N2 * HID / 4 + 255) / 256, blk>>>(w2, w2h, N2 * HID / 4);

    // fc1 + fused LIF scan (emits packed spike bits + flags)
    hgemm_fc1_lif<<<dim3(N1 / BN, M1 / BM), blk, SMEM_TOTAL>>>(x16, w1h);

    // exact fixup for flagged neurons (flips bits)
    fixup_kernel<<<512, 128>>>(x, w1);

    // fc2: out = spk @ w2h^T  (A decoded from bits via LUT; un-permute in epilogue)
    hgemm_fc2<<<dim3(N2 / BN, M1 / BM), blk, SMEM_TOTAL>>>(spkbits, w2h, out);

    write_rate_kernel<<<1, 1>>>(out, out_size - 1);
}

// round 11
// speedup vs baseline: 1.0783x; 1.0783x over previous
#include <cuda_runtime.h>
#include <cuda_fp16.h>
#include <cstdint>
#include <cstddef>

// Problem dims (fixed)
#define M1 16384      // b*t*s = 16*4*256
#define K1 512        // d
#define N1 2048       // hidden
#define N2 512
#define HID 2048
#define N_SPIKES 33554432.0f  // 2^25

#define TAU 4e-3f     // borderline window; sigma_v ~ 4e-4 -> 10 sigma margin
#define FCAP (1 << 22)

// ---------------------------------------------------------------------------
// Device scratch (no allocation allowed). LIF fused into fc1 epilogue.
// Row order for x16 / spk is PERMUTED: row' = (b*256 + s)*4 + t.
// ---------------------------------------------------------------------------
__device__ __half g_x16[(size_t)M1 * K1];     // fp16(x), (b,s,t) row order
__device__ __half g_w1h[(size_t)N1 * K1];     // fp16(w1)
__device__ __half g_spk[(size_t)M1 * HID];    // spikes (fp16), (b,s,t) row order
__device__ __half g_w2h[(size_t)N2 * HID];    // fp16(w2)
__device__ int    g_count;
__device__ int    g_nflag;
__device__ int    g_flag[FCAP];

// ---------------------------------------------------------------------------
// PTX helpers (baseline sm_80+ ISA: cp.async / ldmatrix / mma.sync)
// ---------------------------------------------------------------------------
__device__ __forceinline__ uint32_t smem_u32(const void* p) {
    uint32_t a;
    asm("{ .reg .u64 t; cvta.to.shared.u64 t, %1; cvt.u32.u64 %0, t; }" : "=r"(a) : "l"(p));
    return a;
}
__device__ __forceinline__ void cp16(uint32_t saddr, const void* g) {
    asm volatile("cp.async.cg.shared.global [%0], [%1], 16;" :: "r"(saddr), "l"(g));
}
__device__ __forceinline__ void ldm_x4(uint32_t* r, uint32_t addr) {
    asm volatile("ldmatrix.sync.aligned.m8n8.x4.shared.b16 {%0,%1,%2,%3}, [%4];"
        : "=r"(r[0]), "=r"(r[1]), "=r"(r[2]), "=r"(r[3]) : "r"(addr));
}
__device__ __forceinline__ void mma16816(float* c, const uint32_t* a, uint32_t b0, uint32_t b1) {
    asm volatile("mma.sync.aligned.m16n8k16.row.col.f32.f16.f16.f32 "
        "{%0,%1,%2,%3}, {%4,%5,%6,%7}, {%8,%9}, {%0,%1,%2,%3};"
        : "+f"(c[0]), "+f"(c[1]), "+f"(c[2]), "+f"(c[3])
        : "r"(a[0]), "r"(a[1]), "r"(a[2]), "r"(a[3]), "r"(b0), "r"(b1));
}

// ---------------------------------------------------------------------------
// GEMM config: 128x128x64 tiles, 3-stage pipeline, 8 warps (32x64 per warp)
// ---------------------------------------------------------------------------
#define BM 128
#define BN 128
#define BK 64
#define STAGES 3
#define A_STAGE_BYTES (BM * BK * 2)                 // 16384
#define STAGE_BYTES   (A_STAGE_BYTES + BN * BK * 2) // 32768
#define SMEM_TOTAL    (STAGES * STAGE_BYTES)        // 98304 (>= 128*132*4 epi)

__device__ __forceinline__ void load_stage(uint32_t s_stage, const __half* Ag,
                                           const __half* Bg, int K, int k0, int tid) {
#pragma unroll
    for (int i = 0; i < 4; i++) {
        int c = tid + i * 256;
        int row = c >> 3, kc = c & 7;
        uint32_t so = s_stage + row * 128 + ((kc ^ (row & 7)) << 4);
        cp16(so, Ag + (long)row * K + k0 + kc * 8);
    }
#pragma unroll
    for (int i = 0; i < 4; i++) {
        int c = tid + i * 256;
        int row = c >> 3, kc = c & 7;
        uint32_t so = s_stage + A_STAGE_BYTES + row * 128 + ((kc ^ (row & 7)) << 4);
        cp16(so, Bg + (long)row * K + k0 + kc * 8);
    }
}

// Fragment load for one k16 step into register buffer `buf`
#define LOAD_FRAG(buf, sa_, sb_, ks_) do {                                         \
    const int kch_ = ((ks_) << 1) + (lane >> 4);                                   \
    _Pragma("unroll")                                                              \
    for (int mt = 0; mt < 2; mt++) {                                               \
        int row = wm * 32 + mt * 16 + (lane & 15);                                 \
        ldm_x4(arf[buf][mt], (sa_) + row * 128 + ((kch_ ^ (row & 7)) << 4));       \
    }                                                                              \
    _Pragma("unroll")                                                              \
    for (int np = 0; np < 4; np++) {                                               \
        int row = wn * 64 + np * 16 + (lane & 15);                                 \
        ldm_x4(brf[buf][np], (sb_) + row * 128 + ((kch_ ^ (row & 7)) << 4));       \
    }                                                                              \
} while (0)

// Stage compute with ks-level register double buffering: LDSMs for ks+1 are
// issued before the MMAs of ks, hiding the ~29cyc shared-load latency.
#define STAGE_COMPUTE(sa_, sb_)                                                    \
    LOAD_FRAG(0, sa_, sb_, 0);                                                     \
    _Pragma("unroll")                                                              \
    for (int ks = 0; ks < 4; ks++) {                                               \
        const int cur = ks & 1;                                                    \
        if (ks < 3) LOAD_FRAG(cur ^ 1, sa_, sb_, ks + 1);                          \
        _Pragma("unroll")                                                          \
        for (int mt = 0; mt < 2; mt++)                                             \
            _Pragma("unroll")                                                      \
            for (int nt = 0; nt < 8; nt++)                                         \
                mma16816(acc[mt][nt], arf[cur][mt], brf[cur][nt >> 1][nt & 1],     \
                         brf[cur][nt >> 1][(nt & 1) + 2]);                         \
    }

// ---------------------------------------------------------------------------
// fc1 + fused LIF: A rows (b,s,t)-ordered; epilogue scans t in-tile, writes
// fp16 spikes, flags borderline neurons, counts unflagged spikes.
// ---------------------------------------------------------------------------
__global__ __launch_bounds__(256, 2) void hgemm_fc1_lif(const __half* __restrict__ A,
                                                        const __half* __restrict__ B) {
    extern __shared__ char sm[];
    const uint32_t s_base = smem_u32(sm);
    const int tid = threadIdx.x;
    const int wid = tid >> 5, lane = tid & 31;
    const int wm = wid & 3;
    const int wn = wid >> 2;
    const long bm = (long)blockIdx.y * BM;
    const long bn = (long)blockIdx.x * BN;

    const __half* Ag = A + bm * K1;
    const __half* Bg = B + bn * K1;

    float acc[2][8][4];
    uint32_t arf[2][2][4];
    uint32_t brf[2][4][4];
#pragma unroll
    for (int mt = 0; mt < 2; mt++)
#pragma unroll
        for (int nt = 0; nt < 8; nt++)
#pragma unroll
            for (int i = 0; i < 4; i++) acc[mt][nt][i] = 0.0f;

    const int iters = K1 / BK;
    load_stage(s_base, Ag, Bg, K1, 0, tid);
    asm volatile("cp.async.commit_group;" ::: "memory");
    load_stage(s_base + STAGE_BYTES, Ag, Bg, K1, BK, tid);
    asm volatile("cp.async.commit_group;" ::: "memory");
    for (int it = 0; it < iters; it++) {
        asm volatile("cp.async.wait_group 1;" ::: "memory");
        __syncthreads();
        const int nst = it + 2;
        if (nst < iters)
            load_stage(s_base + (nst % STAGES) * STAGE_BYTES, Ag, Bg, K1, nst * BK, tid);
        asm volatile("cp.async.commit_group;" ::: "memory");
        const uint32_t sa = s_base + (it % STAGES) * STAGE_BYTES;
        const uint32_t sb = sa + A_STAGE_BYTES;
        STAGE_COMPUTE(sa, sb)
    }

    // drain all cp.async before repurposing smem
    asm volatile("cp.async.wait_group 0;" ::: "memory");
    __syncthreads();

    // spill accumulators to smem: h[row within tile][col within tile]
    float* smf = (float*)sm;                 // [128][132]
#pragma unroll
    for (int mt = 0; mt < 2; mt++)
#pragma unroll
        for (int nt = 0; nt < 8; nt++) {
            int r0 = wm * 32 + mt * 16 + (lane >> 2);
            int c  = wn * 64 + nt * 8 + (lane & 3) * 2;
            smf[r0 * 132 + c]       = acc[mt][nt][0];
            smf[r0 * 132 + c + 1]   = acc[mt][nt][1];
            smf[(r0 + 8) * 132 + c]     = acc[mt][nt][2];
            smf[(r0 + 8) * 132 + c + 1] = acc[mt][nt][3];
        }
    __syncthreads();

    // LIF scan: 32 groups x 128 cols = 4096 scans, 16 per thread
    const __half one  = __float2half_rn(1.0f);
    const __half zero = __float2half_rn(0.0f);
    int total = 0;
#pragma unroll
    for (int k16 = 0; k16 < 16; k16++) {
        int id = tid + k16 * 256;
        int q  = id >> 7;             // group within tile (0..31)
        int c  = id & 127;            // col within tile
        long gq = blockIdx.y * 32 + q;        // global (b*256+s)
        long j  = bn + c;                     // hidden index

        float v = 0.0f;
        int cnt = 0;
        bool flagged = false;
#pragma unroll
        for (int t = 0; t < 4; t++) {
            float h = smf[(4 * q + t) * 132 + c];
            v = fmaf(0.95f, v, h);
            flagged |= fabsf(v - 1.0f) < TAU;
            bool fire = (v - 1.0f) > 0.0f;
            g_spk[(gq * 4 + t) * HID + j] = fire ? one : zero;
            cnt += fire ? 1 : 0;
            v = fire ? 0.0f : v;
        }
        if (flagged) {
            int slot = atomicAdd(&g_nflag, 1);
            if (slot < FCAP) g_flag[slot] = (int)(gq * 2048 + j);
        } else {
            total += cnt;
        }
    }
#pragma unroll
    for (int o = 16; o > 0; o >>= 1) total += __shfl_down_sync(0xffffffffu, total, o);
    if (lane == 0 && total) atomicAdd(&g_count, total);
}

// ---------------------------------------------------------------------------
// fc2: A = spikes in (b,s,t) row order; epilogue un-permutes to (b,t,s) rows.
// ---------------------------------------------------------------------------
__global__ __launch_bounds__(256, 2) void hgemm_fc2(const __half* __restrict__ A,
                                                    const __half* __restrict__ B,
                                                    float* __restrict__ C) {
    extern __shared__ char sm[];
    const uint32_t s_base = smem_u32(sm);
    const int tid = threadIdx.x;
    const int wid = tid >> 5, lane = tid & 31;
    const int wm = wid & 3;
    const int wn = wid >> 2;
    const long bm = (long)blockIdx.y * BM;
    const long bn = (long)blockIdx.x * BN;

    const __half* Ag = A + bm * HID;
    const __half* Bg = B + bn * HID;

    float acc[2][8][4];
    uint32_t arf[2][2][4];
    uint32_t brf[2][4][4];
#pragma unroll
    for (int mt = 0; mt < 2; mt++)
#pragma unroll
        for (int nt = 0; nt < 8; nt++)
#pragma unroll
            for (int i = 0; i < 4; i++) acc[mt][nt][i] = 0.0f;

    const int iters = HID / BK;
    load_stage(s_base, Ag, Bg, HID, 0, tid);
    asm volatile("cp.async.commit_group;" ::: "memory");
    load_stage(s_base + STAGE_BYTES, Ag, Bg, HID, BK, tid);
    asm volatile("cp.async.commit_group;" ::: "memory");
    for (int it = 0; it < iters; it++) {
        asm volatile("cp.async.wait_group 1;" ::: "memory");
        __syncthreads();
        const int nst = it + 2;
        if (nst < iters)
            load_stage(s_base + (nst % STAGES) * STAGE_BYTES, Ag, Bg, HID, nst * BK, tid);
        asm volatile("cp.async.commit_group;" ::: "memory");
        const uint32_t sa = s_base + (it % STAGES) * STAGE_BYTES;
        const uint32_t sb = sa + A_STAGE_BYTES;
        STAGE_COMPUTE(sa, sb)
    }

    // epilogue: map row' (b,s,t) -> out row (b,t,s)
#pragma unroll
    for (int mt = 0; mt < 2; mt++)
#pragma unroll
        for (int nt = 0; nt < 8; nt++) {
            long rp0 = bm + wm * 32 + mt * 16 + (lane >> 2);
            long rp1 = rp0 + 8;
            long c = bn + wn * 64 + nt * 8 + (lane & 3) * 2;
            long b0 = rp0 >> 10, s0 = (rp0 >> 2) & 255, t0 = rp0 & 3;
            long b1 = rp1 >> 10, s1 = (rp1 >> 2) & 255, t1 = rp1 & 3;
            long r0 = b0 * 1024 + t0 * 256 + s0;
            long r1 = b1 * 1024 + t1 * 256 + s1;
            *(float2*)(C + r0 * N2 + c) = make_float2(acc[mt][nt][0], acc[mt][nt][1]);
            *(float2*)(C + r1 * N2 + c) = make_float2(acc[mt][nt][2], acc[mt][nt][3]);
        }
}

// ---------------------------------------------------------------------------
// Single prep kernel: casts x (with (b,t,s)->(b,s,t) row permutation), w1, w2.
// ---------------------------------------------------------------------------
#define X4   (M1 * K1 / 4)      // 2097152
#define W14  (N1 * K1 / 4)      // 262144
#define W24  (N2 * HID / 4)     // 262144

__global__ __launch_bounds__(256) void prep_kernel(const float* __restrict__ x,
                                                   const float* __restrict__ w1,
                                                   const float* __restrict__ w2) {
    int i = blockIdx.x * blockDim.x + threadIdx.x;
    if (i < X4) {
        int row = i >> 7;            // 128 float4 per row (K1=512)
        int within = i & 127;
        int b = row >> 10, t = (row >> 8) & 3, s = row & 255;
        long newrow = (((long)b * 256 + s) * 4 + t);
        float4 v = ((const float4*)x)[i];
        __half2* dst = (__half2*)(g_x16 + newrow * K1 + within * 4);
        dst[0] = __floats2half2_rn(v.x, v.y);
        dst[1] = __floats2half2_rn(v.z, v.w);
    } else if (i < X4 + W14) {
        int k = i - X4;
        float4 v = ((const float4*)w1)[k];
        ((__half2*)g_w1h)[2 * k]     = __floats2half2_rn(v.x, v.y);
        ((__half2*)g_w1h)[2 * k + 1] = __floats2half2_rn(v.z, v.w);
    } else if (i < X4 + W14 + W24) {
        int k = i - X4 - W14;
        float4 v = ((const float4*)w2)[k];
        ((__half2*)g_w2h)[2 * k]     = __floats2half2_rn(v.x, v.y);
        ((__half2*)g_w2h)[2 * k + 1] = __floats2half2_rn(v.z, v.w);
    }
}

__global__ void zero_count_kernel() { g_count = 0; g_nflag = 0; }

// ---------------------------------------------------------------------------
// Exact fixup for flagged neurons (bit-identical to R1's 0-flip arithmetic).
// ---------------------------------------------------------------------------
__global__ __launch_bounds__(128) void fixup_kernel(const float* __restrict__ x,
                                                    const float* __restrict__ w1) {
    int n = g_nflag;
    if (n > FCAP) n = FCAP;
    const int stride = gridDim.x * blockDim.x;
    const __half one  = __float2half_rn(1.0f);
    const __half zero = __float2half_rn(0.0f);

    for (int i = blockIdx.x * blockDim.x + threadIdx.x; i < n; i += stride) {
        int idx = g_flag[i];
        int j  = idx & (HID - 1);
        int gq = idx >> 11;           // b*256 + s
        int b  = gq >> 8;
        int s  = gq & 255;
        const float4* wrow = (const float4*)(w1 + (size_t)j * K1);

        float v = 0.0f;
        int c = 0;
#pragma unroll
        for (int tt = 0; tt < 4; tt++) {
            const float4* xrow = (const float4*)(x + (((size_t)b * 4 + tt) * 256 + s) * K1);
            float h = 0.0f;
            for (int k = 0; k < K1 / 4; k++) {
                float4 xv = __ldg(xrow + k);
                float4 wv = __ldg(wrow + k);
                h = fmaf(xv.x, wv.x, h);
                h = fmaf(xv.y, wv.y, h);
                h = fmaf(xv.z, wv.z, h);
                h = fmaf(xv.w, wv.w, h);
            }
            v = fmaf(0.95f, v, h);
            bool fire = (v - 1.0f) > 0.0f;
            g_spk[((size_t)gq * 4 + tt) * HID + j] = fire ? one : zero;
            c += fire ? 1 : 0;
            v = fire ? 0.0f : v;
        }
        if (c) atomicAdd(&g_count, c);
    }
}

__global__ void write_rate_kernel(float* __restrict__ out, int pos) {
    out[pos] = (float)g_count * (1.0f / N_SPIKES);  // exact: count / 2^25
}

// ---------------------------------------------------------------------------
extern "C" void kernel_launch(void* const* d_in, const int* in_sizes, int n_in,
                              void* d_out, int out_size) {
    const float* x  = (const float*)d_in[0];  // (16,4,256,512)
    const float* w1 = (const float*)d_in[1];  // (2048,512)
    const float* w2 = (const float*)d_in[2];  // (512,2048)
    float* out = (float*)d_out;

    __half *x16, *w1h, *spk, *w2h;
    cudaGetSymbolAddress((void**)&x16, g_x16);
    cudaGetSymbolAddress((void**)&w1h, g_w1h);
    cudaGetSymbolAddress((void**)&spk, g_spk);
    cudaGetSymbolAddress((void**)&w2h, g_w2h);

    cudaFuncSetAttribute(hgemm_fc1_lif, cudaFuncAttributeMaxDynamicSharedMemorySize, SMEM_TOTAL);
    cudaFuncSetAttribute(hgemm_fc2, cudaFuncAttributeMaxDynamicSharedMemorySize, SMEM_TOTAL);

    dim3 blk(256);

    zero_count_kernel<<<1, 1>>>();

    // single fused cast/permute pass
    prep_kernel<<<(X4 + W14 + W24 + 255) / 256, blk>>>(x, w1, w2);

    // fc1 + fused LIF scan (writes fp16 spikes + flags; counts unflagged)
    hgemm_fc1_lif<<<dim3(N1 / BN, M1 / BM), blk, SMEM_TOTAL>>>(x16, w1h);

    // exact fixup for flagged neurons
    fixup_kernel<<<512, 128>>>(x, w1);

    // fc2: out = spk @ w2h^T  (row un-permutation in epilogue)
    hgemm_fc2<<<dim3(N2 / BN, M1 / BM), blk, SMEM_TOTAL>>>(spk, w2h, out);

    write_rate_kernel<<<1, 1>>>(out, out_size - 1);
}

// round 12
// speedup vs baseline: 1.7616x; 1.6336x over previous
#include <cuda_runtime.h>
#include <cuda_fp16.h>
#include <cstdint>
#include <cstddef>

// Problem dims (fixed)
#define M1 16384      // b*t*s = 16*4*256
#define K1 512        // d
#define N1 2048       // hidden
#define N2 512
#define HID 2048
#define N_SPIKES 33554432.0f  // 2^25

#define TAU 4e-3f     // borderline window; sigma_v ~ 4e-4 -> 10 sigma margin
#define NGQ 4096      // distinct (b*256+s) groups

// ---------------------------------------------------------------------------
// Device scratch (no allocation allowed). LIF fused into fc1 epilogue.
// Row order for x16 / spk is PERMUTED: row' = (b*256 + s)*4 + t.
// ---------------------------------------------------------------------------
__device__ __half    g_x16[(size_t)M1 * K1];     // fp16(x), (b,s,t) row order
__device__ __half    g_w1h[(size_t)N1 * K1];     // fp16(w1)
__device__ __half    g_spk[(size_t)M1 * HID];    // spikes (fp16), (b,s,t) row order
__device__ __half    g_w2h[(size_t)N2 * HID];    // fp16(w2)
__device__ int       g_count;
__device__ uint32_t  g_flagbits[NGQ * 64];       // per-(gq, j-block) borderline mask

// ---------------------------------------------------------------------------
// PTX helpers (baseline sm_80+ ISA: cp.async / ldmatrix / mma.sync)
// ---------------------------------------------------------------------------
__device__ __forceinline__ uint32_t smem_u32(const void* p) {
    uint32_t a;
    asm("{ .reg .u64 t; cvta.to.shared.u64 t, %1; cvt.u32.u64 %0, t; }" : "=r"(a) : "l"(p));
    return a;
}
__device__ __forceinline__ void cp16(uint32_t saddr, const void* g) {
    asm volatile("cp.async.cg.shared.global [%0], [%1], 16;" :: "r"(saddr), "l"(g));
}
__device__ __forceinline__ void ldm_x4(uint32_t* r, uint32_t addr) {
    asm volatile("ldmatrix.sync.aligned.m8n8.x4.shared.b16 {%0,%1,%2,%3}, [%4];"
        : "=r"(r[0]), "=r"(r[1]), "=r"(r[2]), "=r"(r[3]) : "r"(addr));
}
__device__ __forceinline__ void mma16816(float* c, const uint32_t* a, uint32_t b0, uint32_t b1) {
    asm volatile("mma.sync.aligned.m16n8k16.row.col.f32.f16.f16.f32 "
        "{%0,%1,%2,%3}, {%4,%5,%6,%7}, {%8,%9}, {%0,%1,%2,%3};"
        : "+f"(c[0]), "+f"(c[1]), "+f"(c[2]), "+f"(c[3])
        : "r"(a[0]), "r"(a[1]), "r"(a[2]), "r"(a[3]), "r"(b0), "r"(b1));
}

// ---------------------------------------------------------------------------
// GEMM config: 128x128x64 tiles, 3-stage pipeline, 8 warps (32x64 per warp)
// ---------------------------------------------------------------------------
#define BM 128
#define BN 128
#define BK 64
#define STAGES 3
#define A_STAGE_BYTES (BM * BK * 2)                 // 16384
#define STAGE_BYTES   (A_STAGE_BYTES + BN * BK * 2) // 32768
#define SMEM_TOTAL    (STAGES * STAGE_BYTES)        // 98304 (>= 128*132*4 epi)

__device__ __forceinline__ void load_stage(uint32_t s_stage, const __half* Ag,
                                           const __half* Bg, int K, int k0, int tid) {
#pragma unroll
    for (int i = 0; i < 4; i++) {
        int c = tid + i * 256;
        int row = c >> 3, kc = c & 7;
        uint32_t so = s_stage + row * 128 + ((kc ^ (row & 7)) << 4);
        cp16(so, Ag + (long)row * K + k0 + kc * 8);
    }
#pragma unroll
    for (int i = 0; i < 4; i++) {
        int c = tid + i * 256;
        int row = c >> 3, kc = c & 7;
        uint32_t so = s_stage + A_STAGE_BYTES + row * 128 + ((kc ^ (row & 7)) << 4);
        cp16(so, Bg + (long)row * K + k0 + kc * 8);
    }
}

// Fragment load for one k16 step into register buffer `buf`
#define LOAD_FRAG(buf, sa_, sb_, ks_) do {                                         \
    const int kch_ = ((ks_) << 1) + (lane >> 4);                                   \
    _Pragma("unroll")                                                              \
    for (int mt = 0; mt < 2; mt++) {                                               \
        int row = wm * 32 + mt * 16 + (lane & 15);                                 \
        ldm_x4(arf[buf][mt], (sa_) + row * 128 + ((kch_ ^ (row & 7)) << 4));       \
    }                                                                              \
    _Pragma("unroll")                                                              \
    for (int np = 0; np < 4; np++) {                                               \
        int row = wn * 64 + np * 16 + (lane & 15);                                 \
        ldm_x4(brf[buf][np], (sb_) + row * 128 + ((kch_ ^ (row & 7)) << 4));       \
    }                                                                              \
} while (0)

// Stage compute with ks-level register double buffering
#define STAGE_COMPUTE(sa_, sb_)                                                    \
    LOAD_FRAG(0, sa_, sb_, 0);                                                     \
    _Pragma("unroll")                                                              \
    for (int ks = 0; ks < 4; ks++) {                                               \
        const int cur = ks & 1;                                                    \
        if (ks < 3) LOAD_FRAG(cur ^ 1, sa_, sb_, ks + 1);                          \
        _Pragma("unroll")                                                          \
        for (int mt = 0; mt < 2; mt++)                                             \
            _Pragma("unroll")                                                      \
            for (int nt = 0; nt < 8; nt++)                                         \
                mma16816(acc[mt][nt], arf[cur][mt], brf[cur][nt >> 1][nt & 1],     \
                         brf[cur][nt >> 1][(nt & 1) + 2]);                         \
    }

// ---------------------------------------------------------------------------
// fc1 + fused LIF: A rows (b,s,t)-ordered; epilogue scans t in-tile, writes
// fp16 spikes, emits flag-bit masks via ballot, counts unflagged spikes.
// ---------------------------------------------------------------------------
__global__ __launch_bounds__(256, 2) void hgemm_fc1_lif(const __half* __restrict__ A,
                                                        const __half* __restrict__ B) {
    extern __shared__ char sm[];
    const uint32_t s_base = smem_u32(sm);
    const int tid = threadIdx.x;
    const int wid = tid >> 5, lane = tid & 31;
    const int wm = wid & 3;
    const int wn = wid >> 2;
    const long bm = (long)blockIdx.y * BM;
    const long bn = (long)blockIdx.x * BN;

    const __half* Ag = A + bm * K1;
    const __half* Bg = B + bn * K1;

    float acc[2][8][4];
    uint32_t arf[2][2][4];
    uint32_t brf[2][4][4];
#pragma unroll
    for (int mt = 0; mt < 2; mt++)
#pragma unroll
        for (int nt = 0; nt < 8; nt++)
#pragma unroll
            for (int i = 0; i < 4; i++) acc[mt][nt][i] = 0.0f;

    const int iters = K1 / BK;
    load_stage(s_base, Ag, Bg, K1, 0, tid);
    asm volatile("cp.async.commit_group;" ::: "memory");
    load_stage(s_base + STAGE_BYTES, Ag, Bg, K1, BK, tid);
    asm volatile("cp.async.commit_group;" ::: "memory");
    for (int it = 0; it < iters; it++) {
        asm volatile("cp.async.wait_group 1;" ::: "memory");
        __syncthreads();
        const int nst = it + 2;
        if (nst < iters)
            load_stage(s_base + (nst % STAGES) * STAGE_BYTES, Ag, Bg, K1, nst * BK, tid);
        asm volatile("cp.async.commit_group;" ::: "memory");
        const uint32_t sa = s_base + (it % STAGES) * STAGE_BYTES;
        const uint32_t sb = sa + A_STAGE_BYTES;
        STAGE_COMPUTE(sa, sb)
    }

    // drain all cp.async before repurposing smem
    asm volatile("cp.async.wait_group 0;" ::: "memory");
    __syncthreads();

    // spill accumulators to smem: h[row within tile][col within tile]
    float* smf = (float*)sm;                 // [128][132]
#pragma unroll
    for (int mt = 0; mt < 2; mt++)
#pragma unroll
        for (int nt = 0; nt < 8; nt++) {
            int r0 = wm * 32 + mt * 16 + (lane >> 2);
            int c  = wn * 64 + nt * 8 + (lane & 3) * 2;
            smf[r0 * 132 + c]       = acc[mt][nt][0];
            smf[r0 * 132 + c + 1]   = acc[mt][nt][1];
            smf[(r0 + 8) * 132 + c]     = acc[mt][nt][2];
            smf[(r0 + 8) * 132 + c + 1] = acc[mt][nt][3];
        }
    __syncthreads();

    // LIF scan: 32 groups x 128 cols; warp lanes cover 32 consecutive cols of
    // one group -> per-warp ballot gives the 32-bit flag word directly.
    const __half one  = __float2half_rn(1.0f);
    const __half zero = __float2half_rn(0.0f);
    int total = 0;
#pragma unroll
    for (int k16 = 0; k16 < 16; k16++) {
        int id = tid + k16 * 256;
        int q  = id >> 7;             // group within tile (0..31)
        int c  = id & 127;            // col within tile (lane = c & 31)
        long gq = blockIdx.y * 32 + q;        // global (b*256+s)
        long j  = bn + c;                     // hidden index

        float v = 0.0f;
        int cnt = 0;
        bool flagged = false;
#pragma unroll
        for (int t = 0; t < 4; t++) {
            float h = smf[(4 * q + t) * 132 + c];
            v = fmaf(0.95f, v, h);
            flagged |= fabsf(v - 1.0f) < TAU;
            bool fire = (v - 1.0f) > 0.0f;
            g_spk[(gq * 4 + t) * HID + j] = fire ? one : zero;
            cnt += fire ? 1 : 0;
            v = fire ? 0.0f : v;
        }
        uint32_t fmask = __ballot_sync(0xffffffffu, flagged);
        if (lane == 0)
            g_flagbits[gq * 64 + (j >> 5)] = fmask;
        if (!flagged) total += cnt;    // flagged neurons counted in fixup
    }
#pragma unroll
    for (int o = 16; o > 0; o >>= 1) total += __shfl_down_sync(0xffffffffu, total, o);
    if (lane == 0 && total) atomicAdd(&g_count, total);
}

// ---------------------------------------------------------------------------
// fc2: A = spikes in (b,s,t) row order; epilogue un-permutes to (b,t,s) rows.
// ---------------------------------------------------------------------------
__global__ __launch_bounds__(256, 2) void hgemm_fc2(const __half* __restrict__ A,
                                                    const __half* __restrict__ B,
                                                    float* __restrict__ C) {
    extern __shared__ char sm[];
    const uint32_t s_base = smem_u32(sm);
    const int tid = threadIdx.x;
    const int wid = tid >> 5, lane = tid & 31;
    const int wm = wid & 3;
    const int wn = wid >> 2;
    const long bm = (long)blockIdx.y * BM;
    const long bn = (long)blockIdx.x * BN;

    const __half* Ag = A + bm * HID;
    const __half* Bg = B + bn * HID;

    float acc[2][8][4];
    uint32_t arf[2][2][4];
    uint32_t brf[2][4][4];
#pragma unroll
    for (int mt = 0; mt < 2; mt++)
#pragma unroll
        for (int nt = 0; nt < 8; nt++)
#pragma unroll
            for (int i = 0; i < 4; i++) acc[mt][nt][i] = 0.0f;

    const int iters = HID / BK;
    load_stage(s_base, Ag, Bg, HID, 0, tid);
    asm volatile("cp.async.commit_group;" ::: "memory");
    load_stage(s_base + STAGE_BYTES, Ag, Bg, HID, BK, tid);
    asm volatile("cp.async.commit_group;" ::: "memory");
    for (int it = 0; it < iters; it++) {
        asm volatile("cp.async.wait_group 1;" ::: "memory");
        __syncthreads();
        const int nst = it + 2;
        if (nst < iters)
            load_stage(s_base + (nst % STAGES) * STAGE_BYTES, Ag, Bg, HID, nst * BK, tid);
        asm volatile("cp.async.commit_group;" ::: "memory");
        const uint32_t sa = s_base + (it % STAGES) * STAGE_BYTES;
        const uint32_t sb = sa + A_STAGE_BYTES;
        STAGE_COMPUTE(sa, sb)
    }

    // epilogue: map row' (b,s,t) -> out row (b,t,s)
#pragma unroll
    for (int mt = 0; mt < 2; mt++)
#pragma unroll
        for (int nt = 0; nt < 8; nt++) {
            long rp0 = bm + wm * 32 + mt * 16 + (lane >> 2);
            long rp1 = rp0 + 8;
            long c = bn + wn * 64 + nt * 8 + (lane & 3) * 2;
            long b0 = rp0 >> 10, s0 = (rp0 >> 2) & 255, t0 = rp0 & 3;
            long b1 = rp1 >> 10, s1 = (rp1 >> 2) & 255, t1 = rp1 & 3;
            long r0 = b0 * 1024 + t0 * 256 + s0;
            long r1 = b1 * 1024 + t1 * 256 + s1;
            *(float2*)(C + r0 * N2 + c) = make_float2(acc[mt][nt][0], acc[mt][nt][1]);
            *(float2*)(C + r1 * N2 + c) = make_float2(acc[mt][nt][2], acc[mt][nt][3]);
        }
}

// ---------------------------------------------------------------------------
// Single prep kernel: casts x (with (b,t,s)->(b,s,t) row permutation), w1, w2.
// Also zeroes count (flag bits are fully overwritten by fc1, no zeroing needed).
// ---------------------------------------------------------------------------
#define X4   (M1 * K1 / 4)      // 2097152
#define W14  (N1 * K1 / 4)      // 262144
#define W24  (N2 * HID / 4)     // 262144

__global__ __launch_bounds__(256) void prep_kernel(const float* __restrict__ x,
                                                   const float* __restrict__ w1,
                                                   const float* __restrict__ w2) {
    int i = blockIdx.x * blockDim.x + threadIdx.x;
    if (i == 0) g_count = 0;
    if (i < X4) {
        int row = i >> 7;            // 128 float4 per row (K1=512)
        int within = i & 127;
        int b = row >> 10, t = (row >> 8) & 3, s = row & 255;
        long newrow = (((long)b * 256 + s) * 4 + t);
        float4 v = ((const float4*)x)[i];
        __half2* dst = (__half2*)(g_x16 + newrow * K1 + within * 4);
        dst[0] = __floats2half2_rn(v.x, v.y);
        dst[1] = __floats2half2_rn(v.z, v.w);
    } else if (i < X4 + W14) {
        int k = i - X4;
        float4 v = ((const float4*)w1)[k];
        ((__half2*)g_w1h)[2 * k]     = __floats2half2_rn(v.x, v.y);
        ((__half2*)g_w1h)[2 * k + 1] = __floats2half2_rn(v.z, v.w);
    } else if (i < X4 + W14 + W24) {
        int k = i - X4 - W14;
        float4 v = ((const float4*)w2)[k];
        ((__half2*)g_w2h)[2 * k]     = __floats2half2_rn(v.x, v.y);
        ((__half2*)g_w2h)[2 * k + 1] = __floats2half2_rn(v.z, v.w);
    }
}

// ---------------------------------------------------------------------------
// Parallel fixup: one CTA per gq group. Stages the group's 4 fp32 x-rows in
// smem, builds the flagged-j list from the bitmask, then one warp per flagged
// neuron: lane-strided fp32 dot (coalesced w1), shfl tree-reduce, LIF scan.
// ---------------------------------------------------------------------------
__global__ __launch_bounds__(128) void fixup_kernel(const float* __restrict__ x,
                                                    const float* __restrict__ w1) {
    __shared__ float    xs[4][512];     // 8 KB: the 4 timestep rows of this gq
    __shared__ int      list[2048];
    __shared__ int      nlist;
    __shared__ int      blk_count;

    const int tid = threadIdx.x;
    const int lane = tid & 31;
    const int wrp = tid >> 5;
    const int gq = blockIdx.x;          // b*256 + s
    const int b  = gq >> 8;
    const int s  = gq & 255;

    if (tid == 0) { nlist = 0; blk_count = 0; }
    __syncthreads();

    // build flagged-j list from bitmask (64 words, threads 0..63)
    if (tid < 64) {
        uint32_t m = g_flagbits[(size_t)gq * 64 + tid];
        if (m) {
            int base = atomicAdd(&nlist, __popc(m));
            while (m) {
                int bit = __ffs(m) - 1;
                m &= m - 1;
                list[base++] = tid * 32 + bit;
            }
        }
    }
    // stage x rows: 4 rows x 512 floats = 512 float4, 128 threads x 4 iters
#pragma unroll
    for (int i = 0; i < 4; i++) {
        int idx = tid + i * 128;            // 0..511 float4 slots
        int row = idx >> 7, c4 = idx & 127;
        float4 v = __ldg((const float4*)(x + (((size_t)b * 4 + row) * 256 + s) * K1) + c4);
        ((float4*)xs[row])[c4] = v;
    }
    __syncthreads();

    const __half one  = __float2half_rn(1.0f);
    const __half zero = __float2half_rn(0.0f);

    const int n = nlist;
    for (int li = wrp; li < n; li += 4) {
        int j = list[li];
        const float4* wrow = (const float4*)(w1 + (size_t)j * K1);
        float hs[4];
#pragma unroll
        for (int tt = 0; tt < 4; tt++) {
            float p = 0.0f;
#pragma unroll
            for (int k4 = 0; k4 < 4; k4++) {
                int kk = lane + k4 * 32;             // float4 index 0..127
                float4 wv = __ldg(wrow + kk);
                float4 xv = ((const float4*)xs[tt])[kk];
                p = fmaf(xv.x, wv.x, p);
                p = fmaf(xv.y, wv.y, p);
                p = fmaf(xv.z, wv.z, p);
                p = fmaf(xv.w, wv.w, p);
            }
#pragma unroll
            for (int o = 16; o > 0; o >>= 1) p += __shfl_xor_sync(0xffffffffu, p, o);
            hs[tt] = p;
        }
        if (lane == 0) {
            float v = 0.0f;
            int c = 0;
#pragma unroll
            for (int tt = 0; tt < 4; tt++) {
                v = fmaf(0.95f, v, hs[tt]);
                bool fire = (v - 1.0f) > 0.0f;
                g_spk[((size_t)gq * 4 + tt) * HID + j] = fire ? one : zero;
                c += fire ? 1 : 0;
                v = fire ? 0.0f : v;
            }
            if (c) atomicAdd(&blk_count, c);
        }
    }
    __syncthreads();
    if (tid == 0 && blk_count) atomicAdd(&g_count, blk_count);
}

__global__ void write_rate_kernel(float* __restrict__ out, int pos) {
    out[pos] = (float)g_count * (1.0f / N_SPIKES);  // exact: count / 2^25
}

// ---------------------------------------------------------------------------
extern "C" void kernel_launch(void* const* d_in, const int* in_sizes, int n_in,
                              void* d_out, int out_size) {
    const float* x  = (const float*)d_in[0];  // (16,4,256,512)
    const float* w1 = (const float*)d_in[1];  // (2048,512)
    const float* w2 = (const float*)d_in[2];  // (512,2048)
    float* out = (float*)d_out;

    __half *x16, *w1h, *spk, *w2h;
    cudaGetSymbolAddress((void**)&x16, g_x16);
    cudaGetSymbolAddress((void**)&w1h, g_w1h);
    cudaGetSymbolAddress((void**)&spk, g_spk);
    cudaGetSymbolAddress((void**)&w2h, g_w2h);

    cudaFuncSetAttribute(hgemm_fc1_lif, cudaFuncAttributeMaxDynamicSharedMemorySize, SMEM_TOTAL);
    cudaFuncSetAttribute(hgemm_fc2, cudaFuncAttributeMaxDynamicSharedMemorySize, SMEM_TOTAL);

    dim3 blk(256);

    // single fused cast/permute pass (also zeroes the spike counter)
    prep_kernel<<<(X4 + W14 + W24 + 255) / 256, blk>>>(x, w1, w2);

    // fc1 + fused LIF scan (writes fp16 spikes + flag bitmask; counts unflagged)
    hgemm_fc1_lif<<<dim3(N1 / BN, M1 / BM), blk, SMEM_TOTAL>>>(x16, w1h);

    // parallel exact fixup, one CTA per (b,s) group
    fixup_kernel<<<NGQ, 128>>>(x, w1);

    // fc2: out = spk @ w2h^T  (row un-permutation in epilogue)
    hgemm_fc2<<<dim3(N2 / BN, M1 / BM), blk, SMEM_TOTAL>>>(spk, w2h, out);

    write_rate_kernel<<<1, 1>>>(out, out_size - 1);
}